// round 8
// baseline (speedup 1.0000x reference)
#include <cuda_runtime.h>
#include <cuda_bf16.h>
#include <math_constants.h>
#include <cstdint>

// ---------------- problem constants ----------------
#define NPTS 100000
#define DIM  512
#define NQ   2048
#define TOPK 5
#define TM   128
#define TN   128
#define KCH  32                 // K chunk (elements)
#define NCHK (DIM / KCH)        // 16
#define SPLIT 9
#define SLICE 11136             // 87 tiles * 128;  9*11136 >= NPTS
#define RS   80                 // smem row stride bytes (64B data + 16B pad)
#define SZT  (128 * RS)         // 10240 bytes per (operand-half, buffer)

// smem byte offsets
#define OFF_SC   0                       // scores 128 x 132 f32 = 67584
#define OFF_X2S  67584                   // 128 f32 (pad to 512)
#define OFF_AH   68096                   // 2 bufs
#define OFF_AL   (OFF_AH + 2 * SZT)      // 88576
#define OFF_BH   (OFF_AL + 2 * SZT)      // 109056
#define OFF_BL   (OFF_BH + 2 * SZT)      // 129536
#define SMEM_TOT (OFF_BL + 2 * SZT)      // 150016
#define DLO      (2 * SZT)               // hi->lo delta (20480)

// ---------------- scratch ----------------
__device__ float g_x2[NPTS];
__device__ float g_vals[(size_t)NQ * SPLIT * TOPK];
__device__ int   g_idx [(size_t)NQ * SPLIT * TOPK];
// pre-split bf16 operands
__device__ __nv_bfloat16 g_Qh[(size_t)NQ * DIM];
__device__ __nv_bfloat16 g_Ql[(size_t)NQ * DIM];
__device__ __nv_bfloat16 g_Xh[(size_t)NPTS * DIM];
__device__ __nv_bfloat16 g_Xl[(size_t)NPTS * DIM];

// ---------------- helpers ----------------
__device__ __forceinline__ uint32_t smem_u32(const void* p) {
    uint32_t a;
    asm("{ .reg .u64 t; cvta.to.shared.u64 t, %1; cvt.u32.u64 %0, t; }" : "=r"(a) : "l"(p));
    return a;
}
__device__ __forceinline__ uint32_t pack2(float e0, float e1) {
    uint32_t r;  // r = {hi16: bf16(e1), lo16: bf16(e0)}
    asm("cvt.rn.bf16x2.f32 %0, %1, %2;" : "=r"(r) : "f"(e1), "f"(e0));
    return r;
}
__device__ __forceinline__ void cpa16(uint32_t dst, const void* src, int sz) {
    asm volatile("cp.async.cg.shared.global [%0], [%1], 16, %2;"
                 :: "r"(dst), "l"(src), "r"(sz) : "memory");
}
#define CP_COMMIT() asm volatile("cp.async.commit_group;" ::: "memory")
#define CP_WAIT0()  asm volatile("cp.async.wait_group 0;" ::: "memory")

#define LDSM4(R0, R1, R2, R3, ADDR)                                          \
    asm volatile("ldmatrix.sync.aligned.m8n8.x4.shared.b16 {%0,%1,%2,%3}, [%4];" \
                 : "=r"(R0), "=r"(R1), "=r"(R2), "=r"(R3) : "r"(ADDR))
#define MMA(C, A, B0, B1)                                                    \
    asm volatile("mma.sync.aligned.m16n8k16.row.col.f32.bf16.bf16.f32 "     \
                 "{%0,%1,%2,%3}, {%4,%5,%6,%7}, {%8,%9}, {%0,%1,%2,%3};"    \
                 : "+f"((C)[0]), "+f"((C)[1]), "+f"((C)[2]), "+f"((C)[3])   \
                 : "r"((A)[0]), "r"((A)[1]), "r"((A)[2]), "r"((A)[3]),      \
                   "r"(B0), "r"(B1))

__device__ __forceinline__ void top5_ins(float v, int n, float bv[TOPK], int bi[TOPK]) {
    if (v > bv[TOPK - 1]) {
        bv[TOPK - 1] = v; bi[TOPK - 1] = n;
#pragma unroll
        for (int s = TOPK - 1; s > 0; --s) {
            if (bv[s] > bv[s - 1]) {
                float tv = bv[s]; bv[s] = bv[s - 1]; bv[s - 1] = tv;
                int   ti = bi[s]; bi[s] = bi[s - 1]; bi[s - 1] = ti;
            }
        }
    }
}

// ---------------------------------------------------------------------------
// Fused split + (optional) x2: one warp per row of src [nrows x DIM].
// hi = bf16_rn(x), lo = bf16_rn(x - hi). Optionally writes ||row||^2.
// ---------------------------------------------------------------------------
__global__ void split_kernel(const float* __restrict__ src,
                             __nv_bfloat16* __restrict__ hi,
                             __nv_bfloat16* __restrict__ lo,
                             float* __restrict__ x2, int nrows)
{
    int row = (blockIdx.x * blockDim.x + threadIdx.x) >> 5;
    int lane = threadIdx.x & 31;
    if (row >= nrows) return;
    const float4* srow = (const float4*)(src + (size_t)row * DIM);
    uint2* hrow = (uint2*)(hi + (size_t)row * DIM);
    uint2* lrow = (uint2*)(lo + (size_t)row * DIM);
    float s = 0.f;
#pragma unroll
    for (int i = 0; i < DIM / 4 / 32; ++i) {
        float4 v = srow[lane + i * 32];
        s += v.x * v.x + v.y * v.y + v.z * v.z + v.w * v.w;
        uint32_t h01 = pack2(v.x, v.y);
        uint32_t h23 = pack2(v.z, v.w);
        float f0 = __uint_as_float(h01 << 16);
        float f1 = __uint_as_float(h01 & 0xFFFF0000u);
        float f2 = __uint_as_float(h23 << 16);
        float f3 = __uint_as_float(h23 & 0xFFFF0000u);
        uint32_t l01 = pack2(v.x - f0, v.y - f1);
        uint32_t l23 = pack2(v.z - f2, v.w - f3);
        hrow[lane + i * 32] = make_uint2(h01, h23);
        lrow[lane + i * 32] = make_uint2(l01, l23);
    }
    if (x2) {
#pragma unroll
        for (int o = 16; o; o >>= 1) s += __shfl_xor_sync(0xffffffffu, s, o);
        if (lane == 0) x2[row] = s;
    }
}

// ---------------------------------------------------------------------------
// issue cp.async loads for one chunk (A + B, hi + lo) into buffer `buf`.
// 8 x 16B per thread.
// ---------------------------------------------------------------------------
__device__ __forceinline__ void issue_loads(uint32_t sb, int buf, int qbase,
                                            int nTile, int c, int tid)
{
    const int koff = c * KCH;
#pragma unroll
    for (int i = 0; i < 2; ++i) {
        int idx = tid + i * 256;
        int row = idx >> 2, seg = idx & 3;
        const __nv_bfloat16* sH = g_Qh + (size_t)(qbase + row) * DIM + koff + seg * 8;
        const __nv_bfloat16* sL = g_Ql + (size_t)(qbase + row) * DIM + koff + seg * 8;
        uint32_t d = sb + OFF_AH + buf * SZT + row * RS + seg * 16;
        cpa16(d, sH, 16);
        cpa16(d + DLO, sL, 16);
    }
#pragma unroll
    for (int i = 0; i < 2; ++i) {
        int idx = tid + i * 256;
        int row = idx >> 2, seg = idx & 3;
        int xr = nTile + row;
        int ok = xr < NPTS;
        int xs = ok ? xr : 0;
        const __nv_bfloat16* sH = g_Xh + (size_t)xs * DIM + koff + seg * 8;
        const __nv_bfloat16* sL = g_Xl + (size_t)xs * DIM + koff + seg * 8;
        uint32_t d = sb + OFF_BH + buf * SZT + row * RS + seg * 16;
        cpa16(d, sH, ok ? 16 : 0);
        cpa16(d + DLO, sL, ok ? 16 : 0);
    }
}

// ---------------------------------------------------------------------------
// bf16-split HMMA distance GEMM + fused per-slice top-5.
// grid = (16, SPLIT), 256 threads (8 warps, 2x4 warp grid, 64x32 warp tile).
// ---------------------------------------------------------------------------
__global__ __launch_bounds__(256, 1) void knn_main()
{
    extern __shared__ char sm[];
    const uint32_t sb = smem_u32(sm);
    float* Sc  = (float*)(sm + OFF_SC);
    float* x2s = (float*)(sm + OFF_X2S);

    const int tid = threadIdx.x, wid = tid >> 5, lane = tid & 31;
    const int m_off = (wid & 1) * 64;
    const int n_off = (wid >> 1) * 32;
    const int qbase  = blockIdx.x * TM;
    const int nStart = blockIdx.y * SLICE;
    const int nEnd   = min(nStart + SLICE, NPTS);

    const uint32_t aoff = (uint32_t)(m_off + (lane & 15)) * RS + ((lane >> 4) << 4);
    const uint32_t boff = (uint32_t)(n_off + (lane & 7) + ((lane >> 4) << 3)) * RS
                        + (((lane >> 3) & 1) << 4);

    float bv[TOPK]; int bi[TOPK];
#pragma unroll
    for (int s = 0; s < TOPK; ++s) { bv[s] = -CUDART_INF_F; bi[s] = 0; }

    // ---- prologue: first tile's x2s + chunk0 ----
    if (tid < 128) {
        int n = nStart + tid;
        x2s[tid] = (n < nEnd) ? g_x2[n] : 0.f;
    }
    issue_loads(sb, 0, qbase, nStart, 0, tid);
    CP_COMMIT();
    CP_WAIT0();
    __syncthreads();

    int buf = 0;
#pragma unroll 1
    for (int nTile = nStart; nTile < nEnd; nTile += TN) {
        const int colLim = min(TN, nEnd - nTile);

        float acc[4][4][4];
#pragma unroll
        for (int mi = 0; mi < 4; ++mi)
#pragma unroll
            for (int ni = 0; ni < 4; ++ni)
#pragma unroll
                for (int r = 0; r < 4; ++r) acc[mi][ni][r] = 0.f;

#pragma unroll 1
        for (int c = 0; c < NCHK; ++c) {
            const bool inTile = (c + 1 < NCHK);
            const bool hasNext = inTile || (nTile + TN < nEnd);
            if (hasNext) {
                issue_loads(sb, buf ^ 1, qbase, inTile ? nTile : nTile + TN,
                            inTile ? c + 1 : 0, tid);
                CP_COMMIT();
            }

            const uint32_t sAH = sb + OFF_AH + buf * SZT;
            const uint32_t sBH = sb + OFF_BH + buf * SZT;
#pragma unroll
            for (int s = 0; s < 2; ++s) {           // two k16 steps per chunk
                uint32_t ah[4][4], al[4][4], bh[4][2], bl[4][2];
#pragma unroll
                for (int mi = 0; mi < 4; ++mi) {
                    uint32_t adr = sAH + aoff + mi * (16 * RS) + s * 32;
                    LDSM4(ah[mi][0], ah[mi][1], ah[mi][2], ah[mi][3], adr);
                    LDSM4(al[mi][0], al[mi][1], al[mi][2], al[mi][3], adr + DLO);
                }
#pragma unroll
                for (int nj = 0; nj < 2; ++nj) {
                    uint32_t adr = sBH + boff + nj * (16 * RS) + s * 32;
                    uint32_t r0, r1, r2, r3;
                    LDSM4(r0, r1, r2, r3, adr);
                    bh[2 * nj][0] = r0; bh[2 * nj][1] = r1;
                    bh[2 * nj + 1][0] = r2; bh[2 * nj + 1][1] = r3;
                    LDSM4(r0, r1, r2, r3, adr + DLO);
                    bl[2 * nj][0] = r0; bl[2 * nj][1] = r1;
                    bl[2 * nj + 1][0] = r2; bl[2 * nj + 1][1] = r3;
                }
#pragma unroll
                for (int mi = 0; mi < 4; ++mi)
#pragma unroll
                    for (int ni = 0; ni < 4; ++ni) {
                        MMA(acc[mi][ni], ah[mi], bh[ni][0], bh[ni][1]);
                        MMA(acc[mi][ni], ah[mi], bl[ni][0], bl[ni][1]);
                        MMA(acc[mi][ni], al[mi], bh[ni][0], bh[ni][1]);
                    }
            }

            if (hasNext) CP_WAIT0();
            __syncthreads();
            buf ^= 1;
        }

        // ---- epilogue: acc -> Sc (with 2*dot - x2), then row scans ----
        {
            const int rlo = lane >> 2;
            const int cl  = (lane & 3) * 2;
#pragma unroll
            for (int mi = 0; mi < 4; ++mi) {
#pragma unroll
                for (int ni = 0; ni < 4; ++ni) {
                    int col = n_off + ni * 8 + cl;
                    float2 x2p = *(float2*)&x2s[col];
                    int r0 = m_off + mi * 16 + rlo;
                    float2 v0 = make_float2(2.f * acc[mi][ni][0] - x2p.x,
                                            2.f * acc[mi][ni][1] - x2p.y);
                    float2 v1 = make_float2(2.f * acc[mi][ni][2] - x2p.x,
                                            2.f * acc[mi][ni][3] - x2p.y);
                    *(float2*)&Sc[r0 * 132 + col] = v0;
                    *(float2*)&Sc[(r0 + 8) * 132 + col] = v1;
                }
            }
        }
        __syncthreads();

        if (tid < 128) {
#pragma unroll 1
            for (int c = 0; c < colLim; c += 4) {
                float4 v = *(float4*)&Sc[tid * 132 + c];
                top5_ins(v.x, nTile + c + 0, bv, bi);
                top5_ins(v.y, nTile + c + 1, bv, bi);
                top5_ins(v.z, nTile + c + 2, bv, bi);
                top5_ins(v.w, nTile + c + 3, bv, bi);
            }
        }
        __syncthreads();

        // x2s for next tile (next read is after >=1 chunk-loop sync)
        if (nTile + TN < nEnd && tid < 128) {
            int n = nTile + TN + tid;
            x2s[tid] = (n < nEnd) ? g_x2[n] : 0.f;
        }
    }

    if (tid < 128) {
        int q = qbase + tid;
        size_t base = ((size_t)q * SPLIT + blockIdx.y) * TOPK;
#pragma unroll
        for (int s = 0; s < TOPK; ++s) { g_vals[base + s] = bv[s]; g_idx[base + s] = bi[s]; }
    }
}

// ---------------------------------------------------------------------------
__global__ void knn_merge(const int* __restrict__ Y, float* __restrict__ out) {
    int q = blockIdx.x * blockDim.x + threadIdx.x;
    if (q >= NQ) return;
    float bv[TOPK]; int bi[TOPK];
#pragma unroll
    for (int s = 0; s < TOPK; ++s) { bv[s] = -CUDART_INF_F; bi[s] = 0; }
    size_t base = (size_t)q * SPLIT * TOPK;
    for (int c = 0; c < SPLIT * TOPK; ++c) {
        float v = g_vals[base + c];
        if (v > bv[TOPK - 1]) {
            int id = g_idx[base + c];
            bv[TOPK - 1] = v; bi[TOPK - 1] = id;
#pragma unroll
            for (int s = TOPK - 1; s > 0; --s) {
                if (bv[s] > bv[s - 1]) {
                    float tv = bv[s]; bv[s] = bv[s - 1]; bv[s - 1] = tv;
                    int   ti = bi[s]; bi[s] = bi[s - 1]; bi[s - 1] = ti;
                }
            }
        }
    }
    float s = 0.f;
#pragma unroll
    for (int k = 0; k < TOPK; ++k) s += (float)Y[bi[k]];
    out[q * 2 + 0] = s * (1.0f / TOPK);
    out[q * 2 + 1] = 0.f;
}

// ---------------------------------------------------------------------------
extern "C" void kernel_launch(void* const* d_in, const int* in_sizes, int n_in,
                              void* d_out, int out_size) {
    const float* Qm = (const float*)d_in[0];
    const float* X  = (const float*)d_in[1];
    const int*   Y  = (const int*)d_in[2];
    float* out = (float*)d_out;

    cudaFuncSetAttribute(knn_main, cudaFuncAttributeMaxDynamicSharedMemorySize, SMEM_TOT);

    __nv_bfloat16 *qh, *ql, *xh, *xl; float* x2p;
    cudaGetSymbolAddress((void**)&qh, g_Qh);
    cudaGetSymbolAddress((void**)&ql, g_Ql);
    cudaGetSymbolAddress((void**)&xh, g_Xh);
    cudaGetSymbolAddress((void**)&xl, g_Xl);
    cudaGetSymbolAddress((void**)&x2p, g_x2);

    split_kernel<<<(NPTS + 7) / 8, 256>>>(X, xh, xl, x2p, NPTS);
    split_kernel<<<(NQ + 7) / 8, 256>>>(Qm, qh, ql, nullptr, NQ);

    dim3 grid(NQ / TM, SPLIT);
    knn_main<<<grid, 256, SMEM_TOT>>>();

    knn_merge<<<(NQ + 255) / 256, 256>>>(Y, out);
}

// round 11
// speedup vs baseline: 1.8595x; 1.8595x over previous
#include <cuda_runtime.h>
#include <cuda_bf16.h>
#include <math_constants.h>
#include <cstdint>

// ---------------- problem constants ----------------
#define NPTS 100000
#define DIM  512
#define NQ   2048
#define TOPK 5
#define T1   8                  // per-slice candidates kept (phase 1)
#define TM   128
#define TN   128
#define KCH  64                 // K chunk (elements)
#define NCHK (DIM / KCH)        // 8
#define SPLIT 9
#define SLICE 11136             // 87 tiles * 128;  9*11136 >= NPTS
#define NCAND (SPLIT * T1)      // 72 candidates per query
#define RS   144                // smem row stride bytes (128B data + 16B pad)
#define SZT  (128 * RS)         // 18432 bytes per (operand, buffer)

// smem byte offsets (phase-1 kernel)
#define OFF_SC   0                       // scores 128 x 132 f32 = 67584
#define OFF_X2S  67584                   // 128 f32 (pad to 512)
#define OFF_A    68096                   // 2 bufs
#define OFF_B    (OFF_A + 2 * SZT)       // 104960
#define SMEM_TOT (OFF_B + 2 * SZT)       // 141824

// ---------------- scratch ----------------
__device__ float g_x2[NPTS];
__device__ float g_vals[(size_t)NQ * NCAND];
__device__ int   g_idx [(size_t)NQ * NCAND];
__device__ __nv_bfloat16 g_Qb[(size_t)NQ * DIM];
__device__ __nv_bfloat16 g_Xb[(size_t)NPTS * DIM];

// ---------------- helpers ----------------
__device__ __forceinline__ uint32_t smem_u32(const void* p) {
    uint32_t a;
    asm("{ .reg .u64 t; cvta.to.shared.u64 t, %1; cvt.u32.u64 %0, t; }" : "=r"(a) : "l"(p));
    return a;
}
__device__ __forceinline__ uint32_t pack2(float e0, float e1) {
    uint32_t r;  // r = {hi16: bf16(e1), lo16: bf16(e0)}
    asm("cvt.rn.bf16x2.f32 %0, %1, %2;" : "=r"(r) : "f"(e1), "f"(e0));
    return r;
}
__device__ __forceinline__ void cpa16(uint32_t dst, const void* src, int sz) {
    asm volatile("cp.async.cg.shared.global [%0], [%1], 16, %2;"
                 :: "r"(dst), "l"(src), "r"(sz) : "memory");
}
#define CP_COMMIT() asm volatile("cp.async.commit_group;" ::: "memory")
#define CP_WAIT0()  asm volatile("cp.async.wait_group 0;" ::: "memory")

#define LDSM4(R0, R1, R2, R3, ADDR)                                          \
    asm volatile("ldmatrix.sync.aligned.m8n8.x4.shared.b16 {%0,%1,%2,%3}, [%4];" \
                 : "=r"(R0), "=r"(R1), "=r"(R2), "=r"(R3) : "r"(ADDR))
#define MMA(C, A, B0, B1)                                                    \
    asm volatile("mma.sync.aligned.m16n8k16.row.col.f32.bf16.bf16.f32 "     \
                 "{%0,%1,%2,%3}, {%4,%5,%6,%7}, {%8,%9}, {%0,%1,%2,%3};"    \
                 : "+f"((C)[0]), "+f"((C)[1]), "+f"((C)[2]), "+f"((C)[3])   \
                 : "r"((A)[0]), "r"((A)[1]), "r"((A)[2]), "r"((A)[3]),      \
                   "r"(B0), "r"(B1))

template <int D>
__device__ __forceinline__ void topd_ins(float v, int n, float bv[D], int bi[D]) {
    if (v > bv[D - 1]) {
        bv[D - 1] = v; bi[D - 1] = n;
#pragma unroll
        for (int s = D - 1; s > 0; --s) {
            if (bv[s] > bv[s - 1]) {
                float tv = bv[s]; bv[s] = bv[s - 1]; bv[s - 1] = tv;
                int   ti = bi[s]; bi[s] = bi[s - 1]; bi[s - 1] = ti;
            }
        }
    }
}

// ---------------------------------------------------------------------------
// fp32 -> bf16 convert (+ optional ||row||^2). One warp per row.
// ---------------------------------------------------------------------------
__global__ void conv_kernel(const float* __restrict__ src,
                            __nv_bfloat16* __restrict__ dst,
                            float* __restrict__ x2, int nrows)
{
    int row = (blockIdx.x * blockDim.x + threadIdx.x) >> 5;
    int lane = threadIdx.x & 31;
    if (row >= nrows) return;
    const float4* srow = (const float4*)(src + (size_t)row * DIM);
    uint2* drow = (uint2*)(dst + (size_t)row * DIM);
    float s = 0.f;
#pragma unroll
    for (int i = 0; i < DIM / 4 / 32; ++i) {
        float4 v = srow[lane + i * 32];
        s += v.x * v.x + v.y * v.y + v.z * v.z + v.w * v.w;
        drow[lane + i * 32] = make_uint2(pack2(v.x, v.y), pack2(v.z, v.w));
    }
    if (x2) {
#pragma unroll
        for (int o = 16; o; o >>= 1) s += __shfl_xor_sync(0xffffffffu, s, o);
        if (lane == 0) x2[row] = s;
    }
}

// ---------------------------------------------------------------------------
// cp.async fill for one chunk (A + B bf16 tiles) into buffer `buf`.
// 128 rows x 128 bytes each: 4 x 16B per thread per operand.
// ---------------------------------------------------------------------------
__device__ __forceinline__ void issue_loads(uint32_t sb, int buf, int qbase,
                                            int nTile, int c, int tid)
{
    const int koff = c * KCH;
#pragma unroll
    for (int i = 0; i < 4; ++i) {
        int idx = tid + i * 256;
        int row = idx >> 3, seg = idx & 7;
        const __nv_bfloat16* s = g_Qb + (size_t)(qbase + row) * DIM + koff + seg * 8;
        cpa16(sb + OFF_A + buf * SZT + row * RS + seg * 16, s, 16);
    }
#pragma unroll
    for (int i = 0; i < 4; ++i) {
        int idx = tid + i * 256;
        int row = idx >> 3, seg = idx & 7;
        int xr = nTile + row;
        int ok = xr < NPTS;
        const __nv_bfloat16* s = g_Xb + (size_t)(ok ? xr : 0) * DIM + koff + seg * 8;
        cpa16(sb + OFF_B + buf * SZT + row * RS + seg * 16, s, ok ? 16 : 0);
    }
}

// ---------------------------------------------------------------------------
// Phase 1: bf16 HMMA approx-distance GEMM + per-slice top-8 candidates.
// grid = (16, SPLIT), 256 threads (8 warps, 2x4 warp grid, 64x32 warp tile).
// ---------------------------------------------------------------------------
__global__ __launch_bounds__(256, 1) void knn_main()
{
    extern __shared__ char sm[];
    const uint32_t sb = smem_u32(sm);
    float* Sc  = (float*)(sm + OFF_SC);
    float* x2s = (float*)(sm + OFF_X2S);

    const int tid = threadIdx.x, wid = tid >> 5, lane = tid & 31;
    const int m_off = (wid & 1) * 64;
    const int n_off = (wid >> 1) * 32;
    const int qbase  = blockIdx.x * TM;
    const int nStart = blockIdx.y * SLICE;
    const int nEnd   = min(nStart + SLICE, NPTS);

    const uint32_t aoff = (uint32_t)(m_off + (lane & 15)) * RS + ((lane >> 4) << 4);
    const uint32_t boff = (uint32_t)(n_off + (lane & 7) + ((lane >> 4) << 3)) * RS
                        + (((lane >> 3) & 1) << 4);

    float bv[T1]; int bi[T1];
#pragma unroll
    for (int s = 0; s < T1; ++s) { bv[s] = -CUDART_INF_F; bi[s] = 0; }

    // ---- prologue ----
    if (tid < 128) {
        int n = nStart + tid;
        x2s[tid] = (n < nEnd) ? g_x2[n] : 0.f;
    }
    issue_loads(sb, 0, qbase, nStart, 0, tid);
    CP_COMMIT();
    CP_WAIT0();
    __syncthreads();

    int buf = 0;
#pragma unroll 1
    for (int nTile = nStart; nTile < nEnd; nTile += TN) {
        const int colLim = min(TN, nEnd - nTile);

        float acc[4][4][4];
#pragma unroll
        for (int mi = 0; mi < 4; ++mi)
#pragma unroll
            for (int ni = 0; ni < 4; ++ni)
#pragma unroll
                for (int r = 0; r < 4; ++r) acc[mi][ni][r] = 0.f;

#pragma unroll 1
        for (int c = 0; c < NCHK; ++c) {
            const bool inTile = (c + 1 < NCHK);
            const bool hasNext = inTile || (nTile + TN < nEnd);
            if (hasNext) {
                issue_loads(sb, buf ^ 1, qbase, inTile ? nTile : nTile + TN,
                            inTile ? c + 1 : 0, tid);
                CP_COMMIT();
            }

            const uint32_t sA = sb + OFF_A + buf * SZT;
            const uint32_t sB = sb + OFF_B + buf * SZT;
#pragma unroll
            for (int s = 0; s < 4; ++s) {           // four k16 steps per chunk
                uint32_t a[4][4], b[4][2];
#pragma unroll
                for (int mi = 0; mi < 4; ++mi) {
                    uint32_t adr = sA + aoff + mi * (16 * RS) + s * 32;
                    LDSM4(a[mi][0], a[mi][1], a[mi][2], a[mi][3], adr);
                }
#pragma unroll
                for (int nj = 0; nj < 2; ++nj) {
                    uint32_t adr = sB + boff + nj * (16 * RS) + s * 32;
                    uint32_t r0, r1, r2, r3;
                    LDSM4(r0, r1, r2, r3, adr);
                    b[2 * nj][0] = r0; b[2 * nj][1] = r1;
                    b[2 * nj + 1][0] = r2; b[2 * nj + 1][1] = r3;
                }
#pragma unroll
                for (int mi = 0; mi < 4; ++mi)
#pragma unroll
                    for (int ni = 0; ni < 4; ++ni)
                        MMA(acc[mi][ni], a[mi], b[ni][0], b[ni][1]);
            }

            if (hasNext) CP_WAIT0();
            __syncthreads();
            buf ^= 1;
        }

        // ---- epilogue: acc -> Sc (2*dot - x2), then row scans ----
        {
            const int rlo = lane >> 2;
            const int cl  = (lane & 3) * 2;
#pragma unroll
            for (int mi = 0; mi < 4; ++mi) {
#pragma unroll
                for (int ni = 0; ni < 4; ++ni) {
                    int col = n_off + ni * 8 + cl;
                    float2 x2p = *(float2*)&x2s[col];
                    int r0 = m_off + mi * 16 + rlo;
                    float2 v0 = make_float2(2.f * acc[mi][ni][0] - x2p.x,
                                            2.f * acc[mi][ni][1] - x2p.y);
                    float2 v1 = make_float2(2.f * acc[mi][ni][2] - x2p.x,
                                            2.f * acc[mi][ni][3] - x2p.y);
                    *(float2*)&Sc[r0 * 132 + col] = v0;
                    *(float2*)&Sc[(r0 + 8) * 132 + col] = v1;
                }
            }
        }
        __syncthreads();

        if (tid < 128) {
#pragma unroll 1
            for (int c = 0; c < colLim; c += 4) {
                float4 v = *(float4*)&Sc[tid * 132 + c];
                topd_ins<T1>(v.x, nTile + c + 0, bv, bi);
                topd_ins<T1>(v.y, nTile + c + 1, bv, bi);
                topd_ins<T1>(v.z, nTile + c + 2, bv, bi);
                topd_ins<T1>(v.w, nTile + c + 3, bv, bi);
            }
        }
        __syncthreads();

        if (nTile + TN < nEnd && tid < 128) {
            int n = nTile + TN + tid;
            x2s[tid] = (n < nEnd) ? g_x2[n] : 0.f;
        }
    }

    if (tid < 128) {
        int q = qbase + tid;
        size_t base = (size_t)q * NCAND + blockIdx.y * T1;
#pragma unroll
        for (int s = 0; s < T1; ++s) { g_vals[base + s] = bv[s]; g_idx[base + s] = bi[s]; }
    }
}

// ---------------------------------------------------------------------------
// Phase 2: exact fp32 rescore of 72 candidates per query, top-5, vote.
// One block (256 thr) per query.
// ---------------------------------------------------------------------------
__global__ __launch_bounds__(256, 4) void knn_rescore(
    const float* __restrict__ Qm, const float* __restrict__ X,
    const int* __restrict__ Y, float* __restrict__ out)
{
    __shared__ float qrow[DIM];
    __shared__ float cval[NCAND];
    __shared__ int   cidx[NCAND];

    const int q = blockIdx.x;
    const int tid = threadIdx.x, wid = tid >> 5, lane = tid & 31;

    // load query row + candidate indices
    if (tid < 128) *(float4*)&qrow[tid * 4] = *(const float4*)(Qm + (size_t)q * DIM + tid * 4);
    if (tid < NCAND) cidx[tid] = g_idx[(size_t)q * NCAND + tid];
    __syncthreads();

    // exact scores: one warp per candidate, round-robin
    for (int c = wid; c < NCAND; c += 8) {
        int n = cidx[c];
        const float4* xr = (const float4*)(X + (size_t)n * DIM);
        const float4* qr = (const float4*)qrow;
        float s = 0.f;
#pragma unroll
        for (int i = 0; i < DIM / 4 / 32; ++i) {
            float4 xv = xr[lane + i * 32];
            float4 qv = qr[lane + i * 32];
            s += xv.x * qv.x + xv.y * qv.y + xv.z * qv.z + xv.w * qv.w;
        }
#pragma unroll
        for (int o = 16; o; o >>= 1) s += __shfl_xor_sync(0xffffffffu, s, o);
        if (lane == 0) cval[c] = 2.f * s - g_x2[n];
    }
    __syncthreads();

    if (tid == 0) {
        float bv[TOPK]; int bi[TOPK];
#pragma unroll
        for (int s = 0; s < TOPK; ++s) { bv[s] = -CUDART_INF_F; bi[s] = 0; }
        for (int c = 0; c < NCAND; ++c) topd_ins<TOPK>(cval[c], cidx[c], bv, bi);
        float v = 0.f;
#pragma unroll
        for (int k = 0; k < TOPK; ++k) v += (float)Y[bi[k]];
        out[q * 2 + 0] = v * (1.0f / TOPK);
        out[q * 2 + 1] = 0.f;
    }
}

// ---------------------------------------------------------------------------
extern "C" void kernel_launch(void* const* d_in, const int* in_sizes, int n_in,
                              void* d_out, int out_size) {
    const float* Qm = (const float*)d_in[0];
    const float* X  = (const float*)d_in[1];
    const int*   Y  = (const int*)d_in[2];
    float* out = (float*)d_out;

    cudaFuncSetAttribute(knn_main, cudaFuncAttributeMaxDynamicSharedMemorySize, SMEM_TOT);

    __nv_bfloat16 *qb, *xb; float* x2p;
    cudaGetSymbolAddress((void**)&qb, g_Qb);
    cudaGetSymbolAddress((void**)&xb, g_Xb);
    cudaGetSymbolAddress((void**)&x2p, g_x2);

    conv_kernel<<<(NPTS + 7) / 8, 256>>>(X, xb, x2p, NPTS);
    conv_kernel<<<(NQ + 7) / 8, 256>>>(Qm, qb, nullptr, NQ);

    dim3 grid(NQ / TM, SPLIT);
    knn_main<<<grid, 256, SMEM_TOT>>>();

    knn_rescore<<<NQ, 256>>>(Qm, X, Y, out);
}

// round 12
// speedup vs baseline: 2.2468x; 1.2083x over previous
#include <cuda_runtime.h>
#include <cuda_bf16.h>
#include <math_constants.h>
#include <cstdint>

// ---------------- problem constants ----------------
#define NPTS 100000
#define DIM  512
#define NQ   2048
#define TOPK 5
#define T1   8                  // per-slice candidates kept (phase 1)
#define TM   128
#define TN   128
#define KCH  64                 // K chunk (elements)
#define NCHK (DIM / KCH)        // 8
#define SPLIT 18
#define SLICE 5632              // 44 tiles * 128;  18*5632 >= NPTS
#define NCAND (SPLIT * T1)      // 144 candidates per query
#define RS   144                // smem row stride bytes (128B data + 16B pad)
#define SZT  (128 * RS)         // 18432 bytes per (operand, buffer)

// smem byte offsets (phase-1 kernel)
#define OFF_SC   0                       // scores 64 x 132 f32 = 33792 (two passes)
#define OFF_X2S  33792                   // 128 f32 (pad to 512)
#define OFF_A    34304                   // 2 bufs
#define OFF_B    (OFF_A + 2 * SZT)       // 71168
#define SMEM_TOT (OFF_B + 2 * SZT)       // 108032  -> 2 CTAs/SM

// ---------------- scratch ----------------
__device__ float g_x2[NPTS];
__device__ int   g_idx[(size_t)NQ * NCAND];
__device__ __nv_bfloat16 g_Qb[(size_t)NQ * DIM];
__device__ __nv_bfloat16 g_Xb[(size_t)NPTS * DIM];

// ---------------- helpers ----------------
__device__ __forceinline__ uint32_t smem_u32(const void* p) {
    uint32_t a;
    asm("{ .reg .u64 t; cvta.to.shared.u64 t, %1; cvt.u32.u64 %0, t; }" : "=r"(a) : "l"(p));
    return a;
}
__device__ __forceinline__ uint32_t pack2(float e0, float e1) {
    uint32_t r;
    asm("cvt.rn.bf16x2.f32 %0, %1, %2;" : "=r"(r) : "f"(e1), "f"(e0));
    return r;
}
__device__ __forceinline__ void cpa16(uint32_t dst, const void* src, int sz) {
    asm volatile("cp.async.cg.shared.global [%0], [%1], 16, %2;"
                 :: "r"(dst), "l"(src), "r"(sz) : "memory");
}
#define CP_COMMIT() asm volatile("cp.async.commit_group;" ::: "memory")
#define CP_WAIT0()  asm volatile("cp.async.wait_group 0;" ::: "memory")

#define LDSM4(R0, R1, R2, R3, ADDR)                                          \
    asm volatile("ldmatrix.sync.aligned.m8n8.x4.shared.b16 {%0,%1,%2,%3}, [%4];" \
                 : "=r"(R0), "=r"(R1), "=r"(R2), "=r"(R3) : "r"(ADDR))
#define MMA(C, A, B0, B1)                                                    \
    asm volatile("mma.sync.aligned.m16n8k16.row.col.f32.bf16.bf16.f32 "     \
                 "{%0,%1,%2,%3}, {%4,%5,%6,%7}, {%8,%9}, {%0,%1,%2,%3};"    \
                 : "+f"((C)[0]), "+f"((C)[1]), "+f"((C)[2]), "+f"((C)[3])   \
                 : "r"((A)[0]), "r"((A)[1]), "r"((A)[2]), "r"((A)[3]),      \
                   "r"(B0), "r"(B1))

template <int D>
__device__ __forceinline__ void topd_ins(float v, int n, float bv[D], int bi[D]) {
    if (v > bv[D - 1]) {
        bv[D - 1] = v; bi[D - 1] = n;
#pragma unroll
        for (int s = D - 1; s > 0; --s) {
            if (bv[s] > bv[s - 1]) {
                float tv = bv[s]; bv[s] = bv[s - 1]; bv[s - 1] = tv;
                int   ti = bi[s]; bi[s] = bi[s - 1]; bi[s - 1] = ti;
            }
        }
    }
}

// ---------------------------------------------------------------------------
// fp32 -> bf16 convert (+ optional ||row||^2). One warp per row.
// ---------------------------------------------------------------------------
__global__ void conv_kernel(const float* __restrict__ src,
                            __nv_bfloat16* __restrict__ dst,
                            float* __restrict__ x2, int nrows)
{
    int row = (blockIdx.x * blockDim.x + threadIdx.x) >> 5;
    int lane = threadIdx.x & 31;
    if (row >= nrows) return;
    const float4* srow = (const float4*)(src + (size_t)row * DIM);
    uint2* drow = (uint2*)(dst + (size_t)row * DIM);
    float s = 0.f;
#pragma unroll
    for (int i = 0; i < DIM / 4 / 32; ++i) {
        float4 v = srow[lane + i * 32];
        s += v.x * v.x + v.y * v.y + v.z * v.z + v.w * v.w;
        drow[lane + i * 32] = make_uint2(pack2(v.x, v.y), pack2(v.z, v.w));
    }
    if (x2) {
#pragma unroll
        for (int o = 16; o; o >>= 1) s += __shfl_xor_sync(0xffffffffu, s, o);
        if (lane == 0) x2[row] = s;
    }
}

// ---------------------------------------------------------------------------
// cp.async fill for one chunk (A + B bf16 tiles) into buffer `buf`.
// ---------------------------------------------------------------------------
__device__ __forceinline__ void issue_loads(uint32_t sb, int buf, int qbase,
                                            int nTile, int c, int tid)
{
    const int koff = c * KCH;
#pragma unroll
    for (int i = 0; i < 4; ++i) {
        int idx = tid + i * 256;
        int row = idx >> 3, seg = idx & 7;
        const __nv_bfloat16* s = g_Qb + (size_t)(qbase + row) * DIM + koff + seg * 8;
        cpa16(sb + OFF_A + buf * SZT + row * RS + seg * 16, s, 16);
    }
#pragma unroll
    for (int i = 0; i < 4; ++i) {
        int idx = tid + i * 256;
        int row = idx >> 3, seg = idx & 7;
        int xr = nTile + row;
        int ok = xr < NPTS;
        const __nv_bfloat16* s = g_Xb + (size_t)(ok ? xr : 0) * DIM + koff + seg * 8;
        cpa16(sb + OFF_B + buf * SZT + row * RS + seg * 16, s, ok ? 16 : 0);
    }
}

// ---------------------------------------------------------------------------
// Phase 1: bf16 HMMA approx-distance GEMM + per-slice top-8 candidates.
// grid = (16, SPLIT), 256 threads, 2 CTAs/SM.
// ---------------------------------------------------------------------------
__global__ __launch_bounds__(256, 2) void knn_main()
{
    extern __shared__ char sm[];
    const uint32_t sb = smem_u32(sm);
    float* Sc  = (float*)(sm + OFF_SC);
    float* x2s = (float*)(sm + OFF_X2S);

    const int tid = threadIdx.x, wid = tid >> 5, lane = tid & 31;
    const int m_off = (wid & 1) * 64;
    const int n_off = (wid >> 1) * 32;
    const int qbase  = blockIdx.x * TM;
    const int nStart = blockIdx.y * SLICE;
    const int nEnd   = min(nStart + SLICE, NPTS);

    const uint32_t aoff = (uint32_t)(m_off + (lane & 15)) * RS + ((lane >> 4) << 4);
    const uint32_t boff = (uint32_t)(n_off + (lane & 7) + ((lane >> 4) << 3)) * RS
                        + (((lane >> 3) & 1) << 4);

    float bv[T1]; int bi[T1];
#pragma unroll
    for (int s = 0; s < T1; ++s) { bv[s] = -CUDART_INF_F; bi[s] = 0; }

    // ---- prologue ----
    if (tid < 128) {
        int n = nStart + tid;
        x2s[tid] = (n < nEnd) ? g_x2[n] : 0.f;
    }
    issue_loads(sb, 0, qbase, nStart, 0, tid);
    CP_COMMIT();
    CP_WAIT0();
    __syncthreads();

    int buf = 0;
#pragma unroll 1
    for (int nTile = nStart; nTile < nEnd; nTile += TN) {
        const int colLim = min(TN, nEnd - nTile);

        float acc[4][4][4];
#pragma unroll
        for (int mi = 0; mi < 4; ++mi)
#pragma unroll
            for (int ni = 0; ni < 4; ++ni)
#pragma unroll
                for (int r = 0; r < 4; ++r) acc[mi][ni][r] = 0.f;

#pragma unroll 1
        for (int c = 0; c < NCHK; ++c) {
            const bool inTile = (c + 1 < NCHK);
            const bool hasNext = inTile || (nTile + TN < nEnd);
            if (hasNext) {
                issue_loads(sb, buf ^ 1, qbase, inTile ? nTile : nTile + TN,
                            inTile ? c + 1 : 0, tid);
                CP_COMMIT();
            }

            const uint32_t sA = sb + OFF_A + buf * SZT;
            const uint32_t sB = sb + OFF_B + buf * SZT;
#pragma unroll
            for (int s = 0; s < 4; ++s) {           // four k16 steps per chunk
                uint32_t a[4][4], b[4][2];
#pragma unroll
                for (int mi = 0; mi < 4; ++mi) {
                    uint32_t adr = sA + aoff + mi * (16 * RS) + s * 32;
                    LDSM4(a[mi][0], a[mi][1], a[mi][2], a[mi][3], adr);
                }
#pragma unroll
                for (int nj = 0; nj < 2; ++nj) {
                    uint32_t adr = sB + boff + nj * (16 * RS) + s * 32;
                    uint32_t r0, r1, r2, r3;
                    LDSM4(r0, r1, r2, r3, adr);
                    b[2 * nj][0] = r0; b[2 * nj][1] = r1;
                    b[2 * nj + 1][0] = r2; b[2 * nj + 1][1] = r3;
                }
#pragma unroll
                for (int mi = 0; mi < 4; ++mi)
#pragma unroll
                    for (int ni = 0; ni < 4; ++ni)
                        MMA(acc[mi][ni], a[mi], b[ni][0], b[ni][1]);
            }

            if (hasNext) CP_WAIT0();
            __syncthreads();
            buf ^= 1;
        }

        // ---- epilogue, two passes over 64-row Sc ----
        const int rlo = lane >> 2;
        const int cl  = (lane & 3) * 2;
#pragma unroll 1
        for (int p = 0; p < 2; ++p) {
            if ((wid & 1) == p) {   // warps whose m_off == p*64 write local rows 0..63
#pragma unroll
                for (int mi = 0; mi < 4; ++mi) {
#pragma unroll
                    for (int ni = 0; ni < 4; ++ni) {
                        int col = n_off + ni * 8 + cl;
                        float2 x2p = *(float2*)&x2s[col];
                        int r0 = mi * 16 + rlo;
                        float2 v0 = make_float2(2.f * acc[mi][ni][0] - x2p.x,
                                                2.f * acc[mi][ni][1] - x2p.y);
                        float2 v1 = make_float2(2.f * acc[mi][ni][2] - x2p.x,
                                                2.f * acc[mi][ni][3] - x2p.y);
                        *(float2*)&Sc[r0 * 132 + col] = v0;
                        *(float2*)&Sc[(r0 + 8) * 132 + col] = v1;
                    }
                }
            }
            __syncthreads();
            // threads [p*64, p*64+64) scan their (consistent) query row = tid
            if ((tid >> 6) == p && tid < 128) {
                const int lrow = tid & 63;
#pragma unroll 1
                for (int c = 0; c < colLim; c += 4) {
                    float4 v = *(float4*)&Sc[lrow * 132 + c];
                    topd_ins<T1>(v.x, nTile + c + 0, bv, bi);
                    topd_ins<T1>(v.y, nTile + c + 1, bv, bi);
                    topd_ins<T1>(v.z, nTile + c + 2, bv, bi);
                    topd_ins<T1>(v.w, nTile + c + 3, bv, bi);
                }
            }
            __syncthreads();
        }

        if (nTile + TN < nEnd && tid < 128) {
            int n = nTile + TN + tid;
            x2s[tid] = (n < nEnd) ? g_x2[n] : 0.f;
        }
    }

    if (tid < 128) {
        int q = qbase + tid;
        size_t base = (size_t)q * NCAND + blockIdx.y * T1;
#pragma unroll
        for (int s = 0; s < T1; ++s) g_idx[base + s] = bi[s];
    }
}

// ---------------------------------------------------------------------------
// Phase 2: exact fp32 rescore of 144 candidates per query, top-5, vote.
// ---------------------------------------------------------------------------
__global__ __launch_bounds__(256, 4) void knn_rescore(
    const float* __restrict__ Qm, const float* __restrict__ X,
    const int* __restrict__ Y, float* __restrict__ out)
{
    __shared__ float qrow[DIM];
    __shared__ float cval[NCAND];
    __shared__ int   cidx[NCAND];

    const int q = blockIdx.x;
    const int tid = threadIdx.x, wid = tid >> 5, lane = tid & 31;

    if (tid < 128) *(float4*)&qrow[tid * 4] = *(const float4*)(Qm + (size_t)q * DIM + tid * 4);
    if (tid < NCAND) cidx[tid] = g_idx[(size_t)q * NCAND + tid];
    __syncthreads();

    for (int c = wid; c < NCAND; c += 8) {
        int n = cidx[c];
        const float4* xr = (const float4*)(X + (size_t)n * DIM);
        const float4* qr = (const float4*)qrow;
        float s = 0.f;
#pragma unroll
        for (int i = 0; i < DIM / 4 / 32; ++i) {
            float4 xv = xr[lane + i * 32];
            float4 qv = qr[lane + i * 32];
            s += xv.x * qv.x + xv.y * qv.y + xv.z * qv.z + xv.w * qv.w;
        }
#pragma unroll
        for (int o = 16; o; o >>= 1) s += __shfl_xor_sync(0xffffffffu, s, o);
        if (lane == 0) cval[c] = 2.f * s - g_x2[n];
    }
    __syncthreads();

    if (tid == 0) {
        float bv[TOPK]; int bi[TOPK];
#pragma unroll
        for (int s = 0; s < TOPK; ++s) { bv[s] = -CUDART_INF_F; bi[s] = 0; }
        for (int c = 0; c < NCAND; ++c) topd_ins<TOPK>(cval[c], cidx[c], bv, bi);
        float v = 0.f;
#pragma unroll
        for (int k = 0; k < TOPK; ++k) v += (float)Y[bi[k]];
        out[q * 2 + 0] = v * (1.0f / TOPK);
        out[q * 2 + 1] = 0.f;
    }
}

// ---------------------------------------------------------------------------
extern "C" void kernel_launch(void* const* d_in, const int* in_sizes, int n_in,
                              void* d_out, int out_size) {
    const float* Qm = (const float*)d_in[0];
    const float* X  = (const float*)d_in[1];
    const int*   Y  = (const int*)d_in[2];
    float* out = (float*)d_out;

    cudaFuncSetAttribute(knn_main, cudaFuncAttributeMaxDynamicSharedMemorySize, SMEM_TOT);

    __nv_bfloat16 *qb, *xb; float* x2p;
    cudaGetSymbolAddress((void**)&qb, g_Qb);
    cudaGetSymbolAddress((void**)&xb, g_Xb);
    cudaGetSymbolAddress((void**)&x2p, g_x2);

    conv_kernel<<<(NPTS + 7) / 8, 256>>>(X, xb, x2p, NPTS);
    conv_kernel<<<(NQ + 7) / 8, 256>>>(Qm, qb, nullptr, NQ);

    dim3 grid(NQ / TM, SPLIT);
    knn_main<<<grid, 256, SMEM_TOT>>>();

    knn_rescore<<<NQ, 256>>>(Qm, X, Y, out);
}